// round 11
// baseline (speedup 1.0000x reference)
#include <cuda_runtime.h>

#define Bn 16
#define Hn 720
#define Wn 1280
#define PLANE (Hn * Wn)
#define NPIX (Bn * PLANE)
#define TPB 256
#define CHUNK 5            // Wn / TPB
#define BIGI (1 << 30)
#define RPB 4              // output rows per k_row block (Hn % RPB == 0)

#define XT 8               // columns per k_col block
#define SEG 120            // segments per column
#define RSEG 6             // rows per segment (SEG*RSEG == Hn)

// Splat accumulator: x=sum(-fx), y=sum(-fy), z=count, w=pad.
// Zero-initialized at module load; k_row zeroes interior rows (y%4 != 3)
// after last use and k_col zeroes boundary rows (y%4 == 3), so the
// all-zero invariant holds on entry to every kernel_launch / graph replay.
__device__ float4 g_splat[NPIX];
// Compressed planar partials after row pass:
//   valid pixel: pXY = final out values, pNH = -1
//   hole pixel : pXY = left/right sums,  pNH = left/right count (0..2)
__device__ float2 g_pXY[NPIX];
__device__ signed char g_pNH[NPIX];

// ---------------------------------------------------------------- scatter
// One RED.128 per valid source pixel (4 corners = 2x2 box-sum in k_row).
__global__ void k_scatter(const float* __restrict__ in) {
    int p = blockIdx.x * blockDim.x + threadIdx.x;
    if (p >= PLANE) return;
    int b = blockIdx.y;
    int y = p / Wn;
    int x = p - y * Wn;

    float fx = in[(size_t)(2 * b    ) * PLANE + p];
    float fy = in[(size_t)(2 * b + 1) * PLANE + p];

    float x2 = (float)x + fx;
    float y2 = (float)y + fy;
    if (!(x2 >= 0.f && y2 >= 0.f && x2 <= (float)(Wn - 1) && y2 <= (float)(Hn - 1)))
        return;

    int xL = (int)floorf(x2); xL = max(0, min(xL, Wn - 1));
    int yT = (int)floorf(y2); yT = max(0, min(yT, Hn - 1));

    float4* dst = &g_splat[(size_t)b * PLANE + yT * Wn + xL];
    atomicAdd(dst, make_float4(-fx, -fy, 1.f, 0.f));

    // Degenerate clamp: corners coincide when x2/y2 hit the exact border.
    // True multiplicity at the single corner is (1+ex)*(1+ey); the box-sum
    // delivers it once, so add the missing (mult-1)*v.
    int ex = (x2 == (float)(Wn - 1));
    int ey = (y2 == (float)(Hn - 1));
    int m = (1 + ex) * (1 + ey) - 1;
    if (m) atomicAdd(dst, make_float4(-fx * m, -fy * m, (float)m, 0.f));
}

// ------------------------------------- box-sum + normalize + row fill
// One block handles RPB consecutive output rows; splat rows are streamed
// through two ping-pong shared buffers (prev / cur).
__global__ __launch_bounds__(TPB) void k_row(float* __restrict__ outp) {
    __shared__ float bufX[2][Wn], bufY[2][Wn], bufC[2][Wn];
    __shared__ float sX[Wn], sY[Wn];
    __shared__ int wLs[8], wRs[8];

    int g = blockIdx.x;                  // g = b*(Hn/RPB) + group
    int b = g / (Hn / RPB);
    int y0 = (g - b * (Hn / RPB)) * RPB;
    size_t bbase = (size_t)b * PLANE;
    int tid = threadIdx.x;
    int lane = tid & 31;
    int wid = tid >> 5;

    // load prev row (y0-1) or zeros into buffer 0
    if (y0 > 0) {
        size_t pb = bbase + (size_t)(y0 - 1) * Wn;
        for (int i = tid; i < Wn; i += TPB) {
            float4 a = g_splat[pb + i];
            bufX[0][i] = a.x; bufY[0][i] = a.y; bufC[0][i] = a.z;
        }
    } else {
        for (int i = tid; i < Wn; i += TPB) {
            bufX[0][i] = 0.f; bufY[0][i] = 0.f; bufC[0][i] = 0.f;
        }
    }

    int pbuf = 0;
    for (int j = 0; j < RPB; j++) {
        int y = y0 + j;
        size_t base = bbase + (size_t)y * Wn;
        int cbuf = pbuf ^ 1;

        // load cur row
        for (int i = tid; i < Wn; i += TPB) {
            float4 a = g_splat[base + i];
            bufX[cbuf][i] = a.x; bufY[cbuf][i] = a.y; bufC[cbuf][i] = a.z;
        }
        __syncthreads();

        // horizontal box fold + normalize (own chunk), build local scans
        int x0 = tid * CHUNK;
        int lloc[CHUNK], rloc[CHUNK];
        bool hk[CHUNK];
        int lm = -1;
        #pragma unroll
        for (int k = 0; k < CHUNK; k++) {
            int xx = x0 + k;
            float ax = bufX[0][xx] + bufX[1][xx];
            float ay = bufY[0][xx] + bufY[1][xx];
            float ac = bufC[0][xx] + bufC[1][xx];
            if (xx > 0) {
                ax += bufX[0][xx - 1] + bufX[1][xx - 1];
                ay += bufY[0][xx - 1] + bufY[1][xx - 1];
                ac += bufC[0][xx - 1] + bufC[1][xx - 1];
            }
            bool h = (ac > 0.f);
            float inv = h ? (1.f / ac) : 0.f;
            sX[xx] = ax * inv;
            sY[xx] = ay * inv;
            hk[k] = h;
            if (h) lm = xx;
            lloc[k] = lm;
        }
        int rm = BIGI;
        #pragma unroll
        for (int k = CHUNK - 1; k >= 0; k--) {
            int xx = x0 + k;
            if (hk[k]) rm = xx;
            rloc[k] = rm;
        }

        // warp shuffle scans (inclusive), then cross-warp combine
        int linc = lm;
        #pragma unroll
        for (int off = 1; off < 32; off <<= 1) {
            int v = __shfl_up_sync(0xffffffffu, linc, off);
            if (lane >= off) linc = max(linc, v);
        }
        int rinc = rm;
        #pragma unroll
        for (int off = 1; off < 32; off <<= 1) {
            int v = __shfl_down_sync(0xffffffffu, rinc, off);
            if (lane + off < 32) rinc = min(rinc, v);
        }
        if (lane == 31) wLs[wid] = linc;
        if (lane == 0)  wRs[wid] = rinc;
        __syncthreads();   // publishes sX/sY + wLs/wRs

        int cL = -1;
        for (int w2 = 0; w2 < wid; w2++) cL = max(cL, wLs[w2]);
        int le = __shfl_up_sync(0xffffffffu, linc, 1);
        int carryL = max(cL, (lane > 0) ? le : -1);

        int cR = BIGI;
        for (int w2 = wid + 1; w2 < 8; w2++) cR = min(cR, wRs[w2]);
        int re = __shfl_down_sync(0xffffffffu, rinc, 1);
        int carryR = min(cR, (lane < 31) ? re : BIGI);

        float* outX = outp + ((size_t)(2 * b    ) * Hn + y) * Wn;
        float* outY = outp + ((size_t)(2 * b + 1) * Hn + y) * Wn;

        #pragma unroll
        for (int k = 0; k < CHUNK; k++) {
            int xx = x0 + k;
            int L = max(carryL, lloc[k]);
            int R = min(carryR, rloc[k]);
            if (L == xx) {     // valid pixel
                float ox = sX[xx], oy = sY[xx];
                outX[xx] = ox;
                outY[xx] = oy;
                g_pXY[base + xx] = make_float2(ox, oy);
                g_pNH[base + xx] = (signed char)(-1);
            } else {           // hole: left/right partial
                float sx = 0.f, sy = 0.f;
                int num = 0;
                if (L >= 0) { sx += sX[L]; sy += sY[L]; num++; }
                if (R < Wn) { sx += sX[R]; sy += sY[R]; num++; }
                g_pXY[base + xx] = make_float2(sx, sy);
                g_pNH[base + xx] = (signed char)num;
            }
        }
        __syncthreads();   // retire prev buffer before next load overwrites it
        pbuf = cbuf;
    }

    // zero interior splat rows y0..y0+RPB-2 (only this block ever read them)
    for (int r = y0; r < y0 + RPB - 1; r++) {
        size_t rb = bbase + (size_t)r * Wn;
        for (int i = tid; i < Wn; i += TPB)
            g_splat[rb + i] = make_float4(0.f, 0.f, 0.f, 0.f);
    }
}

// ------------------------------------------- parallel column fill
// block = (XT columns, SEG segments); each thread holds RSEG rows in regs.
// Also zeroes the boundary splat rows (y % RPB == RPB-1) for the next call.
__global__ __launch_bounds__(XT * SEG, 1) void k_col(float* __restrict__ outp) {
    __shared__ float4 sD[SEG][XT];   // "first valid at/below" scan
    __shared__ float4 sU[SEG][XT];   // "last valid at/above" scan

    int tx = threadIdx.x;
    int ts = threadIdx.y;
    int b  = blockIdx.y;
    int gx = blockIdx.x * XT + tx;
    size_t cbase = (size_t)b * PLANE + gx;
    int y0 = ts * RSEG;

    float rx[RSEG], ry[RSEG], rn[RSEG];

    float4 dsum = make_float4(0.f, 0.f, 0.f, 0.f);   // topmost valid in seg
    float4 usum = make_float4(0.f, 0.f, 0.f, 0.f);   // bottom-most valid in seg
    #pragma unroll
    for (int k = 0; k < RSEG; k++) {
        size_t idx = cbase + (size_t)(y0 + k) * Wn;
        float2 pv = g_pXY[idx];
        signed char nh = g_pNH[idx];
        rx[k] = pv.x; ry[k] = pv.y;
        if (nh < 0) {
            rn[k] = -1.f;
            if (dsum.z == 0.f) dsum = make_float4(pv.x, pv.y, 1.f, 0.f);
            usum = make_float4(pv.x, pv.y, 1.f, 0.f);
        } else {
            rn[k] = (float)nh;
        }
    }
    sD[ts][tx] = dsum;
    sU[ts][tx] = usum;

    // zero boundary splat rows (y % RPB == RPB-1) — restores invariant
    #pragma unroll
    for (int k = 0; k < RSEG; k++) {
        int yy = y0 + k;
        if ((yy & (RPB - 1)) == RPB - 1)
            g_splat[cbase + (size_t)yy * Wn] = make_float4(0.f, 0.f, 0.f, 0.f);
    }
    __syncthreads();

    // Hillis-Steele "nearest valid" scans along segments (both directions)
    for (int off = 1; off < SEG; off <<= 1) {
        float4 myD = sD[ts][tx];
        float4 myU = sU[ts][tx];
        float4 dv = (ts + off < SEG) ? sD[ts + off][tx] : make_float4(0.f, 0.f, 0.f, 0.f);
        float4 uv = (ts >= off)      ? sU[ts - off][tx] : make_float4(0.f, 0.f, 0.f, 0.f);
        __syncthreads();
        if (myD.z == 0.f) sD[ts][tx] = dv;
        if (myU.z == 0.f) sU[ts][tx] = uv;
        __syncthreads();
    }

    float4 cd = (ts + 1 < SEG) ? sD[ts + 1][tx] : make_float4(0.f, 0.f, 0.f, 0.f);
    float4 cu = (ts > 0)       ? sU[ts - 1][tx] : make_float4(0.f, 0.f, 0.f, 0.f);

    // down apply (bottom-up)
    #pragma unroll
    for (int k = RSEG - 1; k >= 0; k--) {
        if (rn[k] < 0.f) {
            cd = make_float4(rx[k], ry[k], 1.f, 0.f);
        } else {
            rx[k] += cd.x; ry[k] += cd.y; rn[k] += cd.z;
        }
    }

    // up apply (top-down) + finalize hole outputs
    float* oX = outp + (size_t)(2 * b    ) * PLANE + gx;
    float* oY = outp + (size_t)(2 * b + 1) * PLANE + gx;
    #pragma unroll
    for (int k = 0; k < RSEG; k++) {
        if (rn[k] < 0.f) {
            cu = make_float4(rx[k], ry[k], 1.f, 0.f);
        } else {
            float sx  = rx[k] + cu.x;
            float sy  = ry[k] + cu.y;
            float num = rn[k] + cu.z;
            float ox = 0.f, oy = 0.f;
            if (num > 0.f) {
                float inv = 1.f / num;
                ox = sx * inv;
                oy = sy * inv;
            }
            size_t off = (size_t)(y0 + k) * Wn;
            oX[off] = ox;
            oY[off] = oy;
        }
    }
}

// ---------------------------------------------------------------- launch
extern "C" void kernel_launch(void* const* d_in, const int* in_sizes, int n_in,
                              void* d_out, int out_size) {
    const float* in = (const float*)d_in[0];
    float* out = (float*)d_out;

    dim3 gs((PLANE + 255) / 256, Bn);
    k_scatter<<<gs, 256>>>(in);

    k_row<<<Bn * (Hn / RPB), TPB>>>(out);

    dim3 gc(Wn / XT, Bn);
    dim3 bc(XT, SEG);
    k_col<<<gc, bc>>>(out);
}

// round 13
// speedup vs baseline: 1.0702x; 1.0702x over previous
#include <cuda_runtime.h>

#define Bn 16
#define Hn 720
#define Wn 1280
#define PLANE (Hn * Wn)
#define NPIX (Bn * PLANE)
#define TPB 256
#define CHUNK 5            // Wn / TPB
#define BIGI (1 << 30)

#define XT 8               // columns per k_col block
#define SEG 120            // segments per column
#define RSEG 6             // rows per segment (SEG*RSEG == Hn)

// Splat accumulator: x=sum(-fx), y=sum(-fy), z=count, w=pad.
// Zero-initialized at module load; k_col restores zeros every call so the
// all-zero invariant holds on entry to every kernel_launch / graph replay.
__device__ float4 g_splat[NPIX];
// Compressed planar partials after row pass:
//   valid pixel: pXY = final out values, pNH = -1
//   hole pixel : pXY = left/right sums,  pNH = left/right count (0..2)
__device__ float2 g_pXY[NPIX];
__device__ signed char g_pNH[NPIX];

// ---------------------------------------------------------------- scatter
// One RED.128 per valid source pixel (4 corners = 2x2 box-sum in k_row).
__global__ void k_scatter(const float* __restrict__ in) {
    int p = blockIdx.x * blockDim.x + threadIdx.x;
    if (p >= PLANE) return;
    int b = blockIdx.y;
    int y = p / Wn;
    int x = p - y * Wn;

    float fx = in[(size_t)(2 * b    ) * PLANE + p];
    float fy = in[(size_t)(2 * b + 1) * PLANE + p];

    float x2 = (float)x + fx;
    float y2 = (float)y + fy;
    if (!(x2 >= 0.f && y2 >= 0.f && x2 <= (float)(Wn - 1) && y2 <= (float)(Hn - 1)))
        return;

    int xL = (int)floorf(x2); xL = max(0, min(xL, Wn - 1));
    int yT = (int)floorf(y2); yT = max(0, min(yT, Hn - 1));

    float4* dst = &g_splat[(size_t)b * PLANE + yT * Wn + xL];
    atomicAdd(dst, make_float4(-fx, -fy, 1.f, 0.f));

    // Degenerate clamp: corners coincide when x2/y2 hit the exact border.
    // True multiplicity at the single corner is (1+ex)*(1+ey); the box-sum
    // delivers it once, so add the missing (mult-1)*v.
    int ex = (x2 == (float)(Wn - 1));
    int ey = (y2 == (float)(Hn - 1));
    int m = (1 + ex) * (1 + ey) - 1;
    if (m) atomicAdd(dst, make_float4(-fx * m, -fy * m, (float)m, 0.f));
}

// ------------------------------------- box-sum + normalize + row fill
__global__ __launch_bounds__(TPB) void k_row(float* __restrict__ outp) {
    __shared__ float tX[Wn], tY[Wn], tC[Wn];   // vertical pair-sum of splat rows
    __shared__ float sX[Wn], sY[Wn];           // normalized values
    __shared__ int wL[8], wR[8];

    int r = blockIdx.x;          // r = b*Hn + y
    int b = r / Hn;
    int y = r - b * Hn;
    size_t base = (size_t)r * Wn;
    int tid = threadIdx.x;
    int lane = tid & 31;
    int wid = tid >> 5;

    // pass 1: load splat rows y-1,y and fold vertically
    for (int i = tid; i < Wn; i += TPB) {
        float4 a = g_splat[base + i];
        float ax = a.x, ay = a.y, ac = a.z;
        if (y > 0) {
            float4 c = g_splat[base - Wn + i];
            ax += c.x; ay += c.y; ac += c.z;
        }
        tX[i] = ax; tY[i] = ay; tC[i] = ac;
    }
    __syncthreads();

    // pass 2: horizontal box fold + normalize (own chunk), build local scans
    int x0 = tid * CHUNK;
    int lloc[CHUNK], rloc[CHUNK];
    bool hk[CHUNK];
    int lm = -1;
    #pragma unroll
    for (int k = 0; k < CHUNK; k++) {
        int xx = x0 + k;
        float ax = tX[xx], ay = tY[xx], ac = tC[xx];
        if (xx > 0) { ax += tX[xx - 1]; ay += tY[xx - 1]; ac += tC[xx - 1]; }
        bool h = (ac > 0.f);
        float inv = h ? (1.f / ac) : 0.f;
        sX[xx] = ax * inv;
        sY[xx] = ay * inv;
        hk[k] = h;
        if (h) lm = xx;
        lloc[k] = lm;
    }
    int rm = BIGI;
    #pragma unroll
    for (int k = CHUNK - 1; k >= 0; k--) {
        int xx = x0 + k;
        if (hk[k]) rm = xx;
        rloc[k] = rm;
    }

    // warp shuffle scans (inclusive), then cross-warp combine
    int linc = lm;
    #pragma unroll
    for (int off = 1; off < 32; off <<= 1) {
        int v = __shfl_up_sync(0xffffffffu, linc, off);
        if (lane >= off) linc = max(linc, v);
    }
    int rinc = rm;
    #pragma unroll
    for (int off = 1; off < 32; off <<= 1) {
        int v = __shfl_down_sync(0xffffffffu, rinc, off);
        if (lane + off < 32) rinc = min(rinc, v);
    }
    if (lane == 31) wL[wid] = linc;
    if (lane == 0)  wR[wid] = rinc;
    __syncthreads();   // also publishes sX/sY

    int cL = -1;
    for (int w2 = 0; w2 < wid; w2++) cL = max(cL, wL[w2]);
    int le = __shfl_up_sync(0xffffffffu, linc, 1);
    int carryL = max(cL, (lane > 0) ? le : -1);

    int cR = BIGI;
    for (int w2 = wid + 1; w2 < 8; w2++) cR = min(cR, wR[w2]);
    int re = __shfl_down_sync(0xffffffffu, rinc, 1);
    int carryR = min(cR, (lane < 31) ? re : BIGI);

    float* outX = outp + ((size_t)(2 * b    ) * Hn + y) * Wn;
    float* outY = outp + ((size_t)(2 * b + 1) * Hn + y) * Wn;

    #pragma unroll
    for (int k = 0; k < CHUNK; k++) {
        int xx = x0 + k;
        int L = max(carryL, lloc[k]);
        int R = min(carryR, rloc[k]);
        if (L == xx) {     // valid pixel
            float ox = sX[xx], oy = sY[xx];
            outX[xx] = ox;
            outY[xx] = oy;
            g_pXY[base + xx] = make_float2(ox, oy);
            g_pNH[base + xx] = (signed char)(-1);
        } else {           // hole: left/right partial
            float sx = 0.f, sy = 0.f;
            int num = 0;
            if (L >= 0) { sx += sX[L]; sy += sY[L]; num++; }
            if (R < Wn) { sx += sX[R]; sy += sY[R]; num++; }
            g_pXY[base + xx] = make_float2(sx, sy);
            g_pNH[base + xx] = (signed char)num;
        }
    }
}

// ------------------------------------------- parallel column fill
// block = (XT columns, SEG segments); each thread holds RSEG rows in regs.
// Also restores the splat accumulator to zero for the next graph replay
// (k_col is latency-bound with bandwidth slack: measured ~free).
__global__ __launch_bounds__(XT * SEG, 1) void k_col(float* __restrict__ outp) {
    __shared__ float4 sD[SEG][XT];   // "first valid at/below" scan
    __shared__ float4 sU[SEG][XT];   // "last valid at/above" scan

    int tx = threadIdx.x;
    int ts = threadIdx.y;
    int b  = blockIdx.y;
    int gx = blockIdx.x * XT + tx;
    size_t cbase = (size_t)b * PLANE + gx;
    int y0 = ts * RSEG;

    float rx[RSEG], ry[RSEG], rn[RSEG];

    float4 dsum = make_float4(0.f, 0.f, 0.f, 0.f);   // topmost valid in seg
    float4 usum = make_float4(0.f, 0.f, 0.f, 0.f);   // bottom-most valid in seg
    #pragma unroll
    for (int k = 0; k < RSEG; k++) {
        size_t idx = cbase + (size_t)(y0 + k) * Wn;
        float2 pv = g_pXY[idx];
        signed char nh = g_pNH[idx];
        rx[k] = pv.x; ry[k] = pv.y;
        if (nh < 0) {
            rn[k] = -1.f;
            if (dsum.z == 0.f) dsum = make_float4(pv.x, pv.y, 1.f, 0.f);
            usum = make_float4(pv.x, pv.y, 1.f, 0.f);
        } else {
            rn[k] = (float)nh;
        }
    }
    sD[ts][tx] = dsum;
    sU[ts][tx] = usum;

    // restore splat accumulator to zero (invariant for next kernel_launch)
    #pragma unroll
    for (int k = 0; k < RSEG; k++)
        g_splat[cbase + (size_t)(y0 + k) * Wn] = make_float4(0.f, 0.f, 0.f, 0.f);
    __syncthreads();

    // Hillis-Steele "nearest valid" scans along segments (both directions)
    for (int off = 1; off < SEG; off <<= 1) {
        float4 myD = sD[ts][tx];
        float4 myU = sU[ts][tx];
        float4 dv = (ts + off < SEG) ? sD[ts + off][tx] : make_float4(0.f, 0.f, 0.f, 0.f);
        float4 uv = (ts >= off)      ? sU[ts - off][tx] : make_float4(0.f, 0.f, 0.f, 0.f);
        __syncthreads();
        if (myD.z == 0.f) sD[ts][tx] = dv;
        if (myU.z == 0.f) sU[ts][tx] = uv;
        __syncthreads();
    }

    float4 cd = (ts + 1 < SEG) ? sD[ts + 1][tx] : make_float4(0.f, 0.f, 0.f, 0.f);
    float4 cu = (ts > 0)       ? sU[ts - 1][tx] : make_float4(0.f, 0.f, 0.f, 0.f);

    // down apply (bottom-up)
    #pragma unroll
    for (int k = RSEG - 1; k >= 0; k--) {
        if (rn[k] < 0.f) {
            cd = make_float4(rx[k], ry[k], 1.f, 0.f);
        } else {
            rx[k] += cd.x; ry[k] += cd.y; rn[k] += cd.z;
        }
    }

    // up apply (top-down) + finalize hole outputs
    float* oX = outp + (size_t)(2 * b    ) * PLANE + gx;
    float* oY = outp + (size_t)(2 * b + 1) * PLANE + gx;
    #pragma unroll
    for (int k = 0; k < RSEG; k++) {
        if (rn[k] < 0.f) {
            cu = make_float4(rx[k], ry[k], 1.f, 0.f);
        } else {
            float sx  = rx[k] + cu.x;
            float sy  = ry[k] + cu.y;
            float num = rn[k] + cu.z;
            float ox = 0.f, oy = 0.f;
            if (num > 0.f) {
                float inv = 1.f / num;
                ox = sx * inv;
                oy = sy * inv;
            }
            size_t off = (size_t)(y0 + k) * Wn;
            oX[off] = ox;
            oY[off] = oy;
        }
    }
}

// ---------------------------------------------------------------- launch
extern "C" void kernel_launch(void* const* d_in, const int* in_sizes, int n_in,
                              void* d_out, int out_size) {
    const float* in = (const float*)d_in[0];
    float* out = (float*)d_out;

    dim3 gs((PLANE + 255) / 256, Bn);
    k_scatter<<<gs, 256>>>(in);

    k_row<<<Bn * Hn, TPB>>>(out);

    dim3 gc(Wn / XT, Bn);
    dim3 bc(XT, SEG);
    k_col<<<gc, bc>>>(out);
}